// round 11
// baseline (speedup 1.0000x reference)
#include <cuda_runtime.h>
#include <math.h>

#define DIMN 2048
#define NH   16
#define HD   128
#define BSZ  2
#define SEQ  2048
#define ROWS (BSZ*SEQ)   // 4096

// Scratch buffers (allocation-free rule: __device__ globals)
__device__ float g_q[ROWS*DIMN];
__device__ float g_k[ROWS*DIMN];
__device__ float g_v[ROWS*DIMN];
__device__ float g_att[ROWS*DIMN];

__device__ __forceinline__ unsigned f2tf32(float x) {
    unsigned r;
    asm("cvt.rna.tf32.f32 %0, %1;" : "=r"(r) : "f"(x));
    return r;
}

__device__ __forceinline__ void mma_tf32(float c[4],
                                         const unsigned a[4],
                                         const unsigned b[2]) {
    asm("mma.sync.aligned.m16n8k8.row.col.f32.tf32.tf32.f32 "
        "{%0,%1,%2,%3}, {%4,%5,%6,%7}, {%8,%9}, {%0,%1,%2,%3};"
        : "+f"(c[0]), "+f"(c[1]), "+f"(c[2]), "+f"(c[3])
        : "r"(a[0]), "r"(a[1]), "r"(a[2]), "r"(a[3]),
          "r"(b[0]), "r"(b[1]));
}

// ---------------------------------------------------------------------------
// TF32 GEMM body: C[M,N] = A[M,K] * B[N,K]^T
// 128x128 tile, BK=32, 256 threads, double-buffered FRAGMENT-ORDER smem:
//   A-frag (mt,ks,lane) -> one uint4  (LDS.128)
//   B-frag (nt,ks,lane) -> one uint2  (LDS.64)
// Fragment gather permutation is applied on the store side.
// ---------------------------------------------------------------------------
#define BM 128
#define BN 128
#define BK 32
#define FBUF 4096                       // words per A (or B) buffer
#define GSMEM (4 * FBUF * 4)            // 65536 bytes

__device__ __forceinline__ void gemm_body(const float* __restrict__ A,
                                          const float* __restrict__ B,
                                          float* __restrict__ C,
                                          int N, int K,
                                          unsigned* __restrict__ sm)
{
    unsigned* As = sm;                  // [2][32 fidx][32 lane][4]
    unsigned* Bs = sm + 2 * FBUF;       // [2][64 fidx][32 lane][2]

    const int tid  = threadIdx.x;
    const int wid  = tid >> 5;
    const int lane = tid & 31;
    const int lq   = lane >> 2;
    const int lr   = lane & 3;
    const int wmi  = wid >> 2;          // 0..1  (m offset = wmi*64)
    const int wni  = wid & 3;           // 0..3  (n offset = wni*32)
    const int m0   = blockIdx.y * BM;
    const int n0   = blockIdx.x * BN;
    const int lrow = tid >> 3;          // 0..31
    const int lc4  = (tid & 7) * 4;     // 0..28

    // Store-side permutation constants (depend only on lrow/lc4)
    const int ksS  = lc4 >> 3;          // 0..3
    const int hiS  = (lc4 >> 2) & 1;    // 0..1
    float c[4][4][4];
    #pragma unroll
    for (int mt = 0; mt < 4; mt++)
        #pragma unroll
        for (int nt = 0; nt < 4; nt++)
            #pragma unroll
            for (int r = 0; r < 4; r++) c[mt][nt][r] = 0.f;

    const float* Ap = A + (size_t)(m0 + lrow) * K + lc4;
    const float* Bp = B + (size_t)(n0 + lrow) * K + lc4;

    float4 ra[4], rb[4];
    #pragma unroll
    for (int it = 0; it < 4; it++) {
        ra[it] = *(const float4*)(Ap + (size_t)(it * 32) * K);
        rb[it] = *(const float4*)(Bp + (size_t)(it * 32) * K);
    }

    // Store one stage into fragment-order buffers
    auto store_stage = [&](int osel) {
        #pragma unroll
        for (int it = 0; it < 4; it++) {
            int row = it * 32 + lrow;
            // A side: row -> (wmi, mt, lq, regbit)
            int awmi = row >> 6, arr = row & 63;
            int amt  = arr >> 4, arq = arr & 15;
            int alq  = arq & 7,  areg = (arq >> 3) & 1;
            unsigned* da = &As[osel + ((((awmi*4 + amt)*4 + ksS)*32) + alq*4)*4
                               + 2*hiS + areg];
            da[0]  = f2tf32(ra[it].x);
            da[4]  = f2tf32(ra[it].y);
            da[8]  = f2tf32(ra[it].z);
            da[12] = f2tf32(ra[it].w);
            // B side: row -> (wni, nt, lq), reg = hiS
            int bwni = row >> 5, brr = row & 31;
            int bnt  = brr >> 3, blq = brr & 7;
            unsigned* db = &Bs[osel + ((((bwni*4 + bnt)*4 + ksS)*32) + blq*4)*2
                               + hiS];
            db[0] = f2tf32(rb[it].x);
            db[2] = f2tf32(rb[it].y);
            db[4] = f2tf32(rb[it].z);
            db[6] = f2tf32(rb[it].w);
        }
    };

    store_stage(0);

    const int NST = K / BK;
    for (int i = 0; i < NST; i++) {
        const int bsel = (i & 1) * FBUF;

        if (i + 1 < NST) {
            const int koff = (i + 1) * BK;
            #pragma unroll
            for (int it = 0; it < 4; it++) {
                ra[it] = *(const float4*)(Ap + (size_t)(it * 32) * K + koff);
                rb[it] = *(const float4*)(Bp + (size_t)(it * 32) * K + koff);
            }
        }

        __syncthreads();   // buffer bsel fully written; other buffer drained

        const unsigned* Abase = &As[bsel + wmi * 16 * 128 + lane * 4];
        const unsigned* Bbase = &Bs[bsel + wni * 16 * 64  + lane * 2];

        #pragma unroll
        for (int ks = 0; ks < 4; ks++) {
            uint4 av[4];
            uint2 bv[4];
            #pragma unroll
            for (int mt = 0; mt < 4; mt++)
                av[mt] = *(const uint4*)&Abase[(mt*4 + ks) * 128];
            #pragma unroll
            for (int nt = 0; nt < 4; nt++)
                bv[nt] = *(const uint2*)&Bbase[(nt*4 + ks) * 64];
            #pragma unroll
            for (int mt = 0; mt < 4; mt++) {
                unsigned af[4] = {av[mt].x, av[mt].y, av[mt].z, av[mt].w};
                #pragma unroll
                for (int nt = 0; nt < 4; nt++) {
                    unsigned bf[2] = {bv[nt].x, bv[nt].y};
                    mma_tf32(c[mt][nt], af, bf);
                }
            }
        }

        if (i + 1 < NST)
            store_stage(((i + 1) & 1) * FBUF);
    }

    #pragma unroll
    for (int mt = 0; mt < 4; mt++) {
        int row = m0 + wmi * 64 + mt * 16 + lq;
        #pragma unroll
        for (int nt = 0; nt < 4; nt++) {
            int col = n0 + wni * 32 + nt * 8 + lr * 2;
            *(float2*)(C + (size_t)row * N + col)       = make_float2(c[mt][nt][0], c[mt][nt][1]);
            *(float2*)(C + (size_t)(row + 8) * N + col) = make_float2(c[mt][nt][2], c[mt][nt][3]);
        }
    }
}

// Fused Q/K/V projection: blockIdx.z selects weight + destination.
__global__ __launch_bounds__(256, 1) void gemm_qkv(const float* __restrict__ x,
                                                   const float* __restrict__ wq,
                                                   const float* __restrict__ wk,
                                                   const float* __restrict__ wv)
{
    extern __shared__ unsigned gsm[];
    const float* B = (blockIdx.z == 0) ? wq : (blockIdx.z == 1) ? wk : wv;
    float*       C = (blockIdx.z == 0) ? g_q : (blockIdx.z == 1) ? g_k : g_v;
    gemm_body(x, B, C, DIMN, DIMN, gsm);
}

// Generic single GEMM (output projection).
__global__ __launch_bounds__(256, 1) void gemm_tf32(const float* __restrict__ A,
                                                    const float* __restrict__ B,
                                                    float* __restrict__ C,
                                                    int M, int N, int K)
{
    extern __shared__ unsigned gsm[];
    gemm_body(A, B, C, N, K, gsm);
}

// ---------------------------------------------------------------------------
// Tensor-core flash attention with FUSED RoPE on Q/K loads. (unchanged)
// ---------------------------------------------------------------------------
#define KSTR 132
#define VSTR 136
#define AT_SMEM ((2*128*128 + 64*KSTR + 64*VSTR) * 4)

__global__ __launch_bounds__(256, 1) void attn_tc(const float* __restrict__ fc,
                                                  const float* __restrict__ fs)
{
    extern __shared__ unsigned sm[];
    unsigned* Qhi = sm;
    unsigned* Qlo = sm + 128*128;
    unsigned* Ks  = sm + 2*128*128;
    unsigned* Vs  = Ks + 64*KSTR;

    const int tid  = threadIdx.x;
    const int wid  = tid >> 5;
    const int lane = tid & 31;
    const int lq   = lane >> 2;
    const int lr   = lane & 3;
    const int qt   = gridDim.x - 1 - blockIdx.x;
    const int h    = blockIdx.y;
    const int b    = blockIdx.z;
    const int q0   = qt * 128;
    const int R0   = wid * 16;

    const float* Qg = g_q + (size_t)(b*SEQ + q0) * DIMN + h * HD;
    const float* Kg = g_k + (size_t)(b*SEQ) * DIMN + h * HD;
    const float* Vg = g_v + (size_t)(b*SEQ) * DIMN + h * HD;

    const float qsc = 0.08838834764831845f;

    #pragma unroll
    for (int it = 0; it < 16; it++) {
        int i  = it * 256 + tid;
        int r  = i >> 5;
        int c4 = (i & 31) * 4;
        float4 v = *(const float4*)(Qg + (size_t)r * DIMN + c4);
        int s = q0 + r;
        int p = c4 >> 1;
        float c0 = fc[s*64 + p],     sn0 = fs[s*64 + p];
        float c1 = fc[s*64 + p + 1], sn1 = fs[s*64 + p + 1];
        float x0 = (v.x * c0 - v.y * sn0) * qsc;
        float y0 = (v.x * sn0 + v.y * c0) * qsc;
        float x1 = (v.z * c1 - v.w * sn1) * qsc;
        float y1 = (v.z * sn1 + v.w * c1) * qsc;
        unsigned h0 = f2tf32(x0), h1 = f2tf32(y0),
                 h2 = f2tf32(x1), h3 = f2tf32(y1);
        unsigned l0 = f2tf32(x0 - __uint_as_float(h0));
        unsigned l1 = f2tf32(y0 - __uint_as_float(h1));
        unsigned l2 = f2tf32(x1 - __uint_as_float(h2));
        unsigned l3 = f2tf32(y1 - __uint_as_float(h3));
        int blk = (c4 >> 2) ^ (r & 7);
        *(uint4*)&Qhi[r * 128 + blk * 4] = make_uint4(h0, h1, h2, h3);
        *(uint4*)&Qlo[r * 128 + blk * 4] = make_uint4(l0, l1, l2, l3);
    }

    float o[16][4];
    #pragma unroll
    for (int n = 0; n < 16; n++)
        #pragma unroll
        for (int r = 0; r < 4; r++) o[n][r] = 0.f;
    float m0r = -1e30f, m1r = -1e30f, l0r = 0.f, l1r = 0.f;

    const int nkt = 2 * qt + 2;
    for (int kt = 0; kt < nkt; kt++) {
        const int k0 = kt * 64;
        __syncthreads();

        #pragma unroll
        for (int it = 0; it < 8; it++) {
            int i  = it * 256 + tid;
            int r  = i >> 5;
            int c4 = (i & 31) * 4;
            float4 kv = *(const float4*)(Kg + (size_t)(k0 + r) * DIMN + c4);
            float4 vv = *(const float4*)(Vg + (size_t)(k0 + r) * DIMN + c4);
            int s = k0 + r;
            int p = c4 >> 1;
            float c0 = fc[s*64 + p],     sn0 = fs[s*64 + p];
            float c1 = fc[s*64 + p + 1], sn1 = fs[s*64 + p + 1];
            float x0 = kv.x * c0 - kv.y * sn0;
            float y0 = kv.x * sn0 + kv.y * c0;
            float x1 = kv.z * c1 - kv.w * sn1;
            float y1 = kv.z * sn1 + kv.w * c1;
            *(uint4*)&Ks[r * KSTR + c4] =
                make_uint4(f2tf32(x0), f2tf32(y0), f2tf32(x1), f2tf32(y1));
            *(uint4*)&Vs[r * VSTR + c4] =
                make_uint4(f2tf32(vv.x), f2tf32(vv.y), f2tf32(vv.z), f2tf32(vv.w));
        }
        __syncthreads();

        float s[8][4];
        #pragma unroll
        for (int j = 0; j < 8; j++)
            #pragma unroll
            for (int r = 0; r < 4; r++) s[j][r] = 0.f;

        #pragma unroll
        for (int ks = 0; ks < 16; ks++) {
            unsigned ah[4], al[4];
            int rA = (R0 + lq) * 128;
            int rB = (R0 + lq + 8) * 128;
            int blk0 = ((2*ks    ) ^ lq) * 4 + lr;
            int blk1 = ((2*ks + 1) ^ lq) * 4 + lr;
            ah[0] = Qhi[rA + blk0]; ah[1] = Qhi[rB + blk0];
            ah[2] = Qhi[rA + blk1]; ah[3] = Qhi[rB + blk1];
            al[0] = Qlo[rA + blk0]; al[1] = Qlo[rB + blk0];
            al[2] = Qlo[rA + blk1]; al[3] = Qlo[rB + blk1];
            #pragma unroll
            for (int j = 0; j < 8; j++) {
                unsigned bf[2];
                bf[0] = Ks[(8*j + lq) * KSTR + 8*ks + lr    ];
                bf[1] = Ks[(8*j + lq) * KSTR + 8*ks + lr + 4];
                mma_tf32(s[j], ah, bf);
                mma_tf32(s[j], al, bf);
            }
        }

        if (kt >= 2 * qt) {
            int grow0 = q0 + R0 + lq;
            int grow1 = grow0 + 8;
            #pragma unroll
            for (int j = 0; j < 8; j++) {
                int gc = k0 + 8*j + 2*lr;
                if (gc     > grow0) s[j][0] = -1e30f;
                if (gc + 1 > grow0) s[j][1] = -1e30f;
                if (gc     > grow1) s[j][2] = -1e30f;
                if (gc + 1 > grow1) s[j][3] = -1e30f;
            }
        }

        float mx0 = -1e30f, mx1 = -1e30f;
        #pragma unroll
        for (int j = 0; j < 8; j++) {
            mx0 = fmaxf(mx0, fmaxf(s[j][0], s[j][1]));
            mx1 = fmaxf(mx1, fmaxf(s[j][2], s[j][3]));
        }
        mx0 = fmaxf(mx0, __shfl_xor_sync(0xffffffffu, mx0, 1));
        mx0 = fmaxf(mx0, __shfl_xor_sync(0xffffffffu, mx0, 2));
        mx1 = fmaxf(mx1, __shfl_xor_sync(0xffffffffu, mx1, 1));
        mx1 = fmaxf(mx1, __shfl_xor_sync(0xffffffffu, mx1, 2));

        float mn0 = fmaxf(m0r, mx0), mn1 = fmaxf(m1r, mx1);
        float f0 = __expf(m0r - mn0), f1 = __expf(m1r - mn1);
        m0r = mn0; m1r = mn1;

        #pragma unroll
        for (int n = 0; n < 16; n++) {
            o[n][0] *= f0; o[n][1] *= f0;
            o[n][2] *= f1; o[n][3] *= f1;
        }

        float sum0 = 0.f, sum1 = 0.f;
        #pragma unroll
        for (int j = 0; j < 8; j++) {
            s[j][0] = __expf(s[j][0] - mn0);
            s[j][1] = __expf(s[j][1] - mn0);
            s[j][2] = __expf(s[j][2] - mn1);
            s[j][3] = __expf(s[j][3] - mn1);
            sum0 += s[j][0] + s[j][1];
            sum1 += s[j][2] + s[j][3];
        }
        sum0 += __shfl_xor_sync(0xffffffffu, sum0, 1);
        sum0 += __shfl_xor_sync(0xffffffffu, sum0, 2);
        sum1 += __shfl_xor_sync(0xffffffffu, sum1, 1);
        sum1 += __shfl_xor_sync(0xffffffffu, sum1, 2);
        l0r = l0r * f0 + sum0;
        l1r = l1r * f1 + sum1;

        const int srcA = lq * 4 + (lr >> 1);
        const int srcB = srcA + 2;
        const bool odd = (lr & 1);
        #pragma unroll
        for (int j = 0; j < 8; j++) {
            float t0 = __shfl_sync(0xffffffffu, s[j][0], srcA);
            float t1 = __shfl_sync(0xffffffffu, s[j][1], srcA);
            float t2 = __shfl_sync(0xffffffffu, s[j][2], srcA);
            float t3 = __shfl_sync(0xffffffffu, s[j][3], srcA);
            float u0 = __shfl_sync(0xffffffffu, s[j][0], srcB);
            float u1 = __shfl_sync(0xffffffffu, s[j][1], srcB);
            float u2 = __shfl_sync(0xffffffffu, s[j][2], srcB);
            float u3 = __shfl_sync(0xffffffffu, s[j][3], srcB);
            unsigned pa[4];
            pa[0] = f2tf32(odd ? t1 : t0);
            pa[1] = f2tf32(odd ? t3 : t2);
            pa[2] = f2tf32(odd ? u1 : u0);
            pa[3] = f2tf32(odd ? u3 : u2);
            #pragma unroll
            for (int n = 0; n < 16; n++) {
                unsigned bf[2];
                bf[0] = Vs[(8*j + lr    ) * VSTR + 8*n + lq];
                bf[1] = Vs[(8*j + lr + 4) * VSTR + 8*n + lq];
                mma_tf32(o[n], pa, bf);
            }
        }
    }

    float inv0 = 1.f / l0r, inv1 = 1.f / l1r;
    float* Og = g_att + (size_t)(b*SEQ + q0 + R0 + lq) * DIMN + h * HD;
    #pragma unroll
    for (int n = 0; n < 16; n++) {
        int col = 8*n + 2*lr;
        *(float2*)(Og + col) = make_float2(o[n][0]*inv0, o[n][1]*inv0);
        *(float2*)(Og + (size_t)8 * DIMN + col) = make_float2(o[n][2]*inv1, o[n][3]*inv1);
    }
}

// ---------------------------------------------------------------------------
// Launch
// ---------------------------------------------------------------------------
extern "C" void kernel_launch(void* const* d_in, const int* in_sizes, int n_in,
                              void* d_out, int out_size)
{
    const float* x  = (const float*)d_in[0];
    const float* fc = (const float*)d_in[2];
    const float* fs = (const float*)d_in[3];
    const float* wq = (const float*)d_in[5];
    const float* wk = (const float*)d_in[6];
    const float* wv = (const float*)d_in[7];
    const float* wo = (const float*)d_in[8];
    float* out = (float*)d_out;

    float* att;
    cudaGetSymbolAddress((void**)&att, g_att);

    cudaFuncSetAttribute(gemm_qkv,
                         cudaFuncAttributeMaxDynamicSharedMemorySize, GSMEM);
    cudaFuncSetAttribute(gemm_tf32,
                         cudaFuncAttributeMaxDynamicSharedMemorySize, GSMEM);
    cudaFuncSetAttribute(attn_tc,
                         cudaFuncAttributeMaxDynamicSharedMemorySize, AT_SMEM);

    dim3 gq(DIMN/128, ROWS/128, 3);    // (16, 32, 3)
    gemm_qkv<<<gq, 256, GSMEM>>>(x, wq, wk, wv);

    dim3 ga(SEQ/128, NH, BSZ);         // (16, 16, 2)
    attn_tc<<<ga, 256, AT_SMEM>>>(fc, fs);

    dim3 gg(DIMN/128, ROWS/128);       // (16, 32)
    gemm_tf32<<<gg, 256, GSMEM>>>(att, wo, out, ROWS, DIMN, DIMN);
}

// round 17
// speedup vs baseline: 1.4241x; 1.4241x over previous
#include <cuda_runtime.h>
#include <math.h>

#define DIMN 2048
#define NH   16
#define HD   128
#define BSZ  2
#define SEQ  2048
#define ROWS (BSZ*SEQ)   // 4096

// Scratch buffers (allocation-free rule: __device__ globals)
__device__ float g_q[ROWS*DIMN];
__device__ float g_k[ROWS*DIMN];
__device__ float g_v[ROWS*DIMN];
__device__ float g_att[ROWS*DIMN];

__device__ __forceinline__ unsigned f2tf32(float x) {
    unsigned r;
    asm("cvt.rna.tf32.f32 %0, %1;" : "=r"(r) : "f"(x));
    return r;
}

__device__ __forceinline__ void mma_tf32(float c[4],
                                         const unsigned a[4],
                                         const unsigned b[2]) {
    asm("mma.sync.aligned.m16n8k8.row.col.f32.tf32.tf32.f32 "
        "{%0,%1,%2,%3}, {%4,%5,%6,%7}, {%8,%9}, {%0,%1,%2,%3};"
        : "+f"(c[0]), "+f"(c[1]), "+f"(c[2]), "+f"(c[3])
        : "r"(a[0]), "r"(a[1]), "r"(a[2]), "r"(a[3]),
          "r"(b[0]), "r"(b[1]));
}

__device__ __forceinline__ unsigned smem_u32(const void* p) {
    unsigned a;
    asm("{ .reg .u64 t; cvta.to.shared.u64 t, %1; cvt.u32.u64 %0, t; }"
        : "=r"(a) : "l"(p));
    return a;
}

__device__ __forceinline__ void cp16(unsigned dst, const void* src) {
    asm volatile("cp.async.ca.shared.global [%0], [%1], 16;"
                 :: "r"(dst), "l"(src) : "memory");
}

// ---------------------------------------------------------------------------
// TF32 GEMM: C[M,N] = A[M,K] * B[N,K]^T
// 128x128 tile, BK=32, 256 threads, cp.async double-buffered raw-f32 smem.
// tf32 conversion happens in the fragment-load path (FMA pipe is idle).
// Low register budget (launch_bounds 256,2) -> 2 CTAs/SM -> 16 warps/SM.
// ---------------------------------------------------------------------------
#define BK 32
#define GST 36                           // words per row (stride pad)
#define GBUFW (128 * GST)                // words per single tile buffer
#define GSMEM (4 * GBUFW * 4)            // 2 bufs x (A+B) = 73728 bytes

__device__ __forceinline__ void gemm_body(const float* __restrict__ A,
                                          const float* __restrict__ B,
                                          float* __restrict__ C,
                                          int N, int K,
                                          float* __restrict__ smf)
{
    float* As = smf;                    // [2][128][GST]
    float* Bs = smf + 2 * GBUFW;

    const int tid  = threadIdx.x;
    const int wid  = tid >> 5;
    const int lane = tid & 31;
    const int lq   = lane >> 2;
    const int lr   = lane & 3;
    const int wm   = (wid >> 2) * 64;   // 0/64
    const int wn   = (wid & 3) * 32;    // 0/32/64/96
    const int m0   = blockIdx.y * 128;
    const int n0   = blockIdx.x * 128;

    const unsigned saA = smem_u32(As);
    const unsigned saB = smem_u32(Bs);

    // cp.async mapping: 8 chunks (16B) per row; 4 rows-worth per thread
    const int crow = tid >> 3;           // base row 0..31 (x4 blocks of 32)
    const int cch  = tid & 7;            // chunk in row

    float c[4][4][4];
    #pragma unroll
    for (int mt = 0; mt < 4; mt++)
        #pragma unroll
        for (int nt = 0; nt < 4; nt++)
            #pragma unroll
            for (int r = 0; r < 4; r++) c[mt][nt][r] = 0.f;

    auto issue_stage = [&](int stage) {
        const int buf = stage & 1;
        const int kof = stage * BK + cch * 4;
        #pragma unroll
        for (int it = 0; it < 4; it++) {
            int row = it * 32 + crow;
            unsigned d = (unsigned)((buf * GBUFW + row * GST + cch * 4) * 4);
            cp16(saA + d, A + (size_t)(m0 + row) * K + kof);
            cp16(saB + d, B + (size_t)(n0 + row) * K + kof);
        }
        asm volatile("cp.async.commit_group;" ::: "memory");
    };

    const int NST = K / BK;
    issue_stage(0);
    issue_stage(1);

    for (int i = 0; i < NST; i++) {
        if (i == NST - 1)
            asm volatile("cp.async.wait_group 0;" ::: "memory");
        else
            asm volatile("cp.async.wait_group 1;" ::: "memory");
        __syncthreads();   // stage i data visible to all

        const float* Af = As + (i & 1) * GBUFW;
        const float* Bf = Bs + (i & 1) * GBUFW;

        #pragma unroll
        for (int ks = 0; ks < 4; ks++) {
            const int kb = ks * 8;
            unsigned af[4][4], bf[4][2];
            #pragma unroll
            for (int mt = 0; mt < 4; mt++) {
                int r = wm + mt * 16;
                af[mt][0] = f2tf32(Af[(r + lq    ) * GST + kb + lr    ]);
                af[mt][1] = f2tf32(Af[(r + lq + 8) * GST + kb + lr    ]);
                af[mt][2] = f2tf32(Af[(r + lq    ) * GST + kb + lr + 4]);
                af[mt][3] = f2tf32(Af[(r + lq + 8) * GST + kb + lr + 4]);
            }
            #pragma unroll
            for (int nt = 0; nt < 4; nt++) {
                int cn = wn + nt * 8;
                bf[nt][0] = f2tf32(Bf[(cn + lq) * GST + kb + lr    ]);
                bf[nt][1] = f2tf32(Bf[(cn + lq) * GST + kb + lr + 4]);
            }
            #pragma unroll
            for (int mt = 0; mt < 4; mt++)
                #pragma unroll
                for (int nt = 0; nt < 4; nt++)
                    mma_tf32(c[mt][nt], af[mt], bf[nt]);
        }

        __syncthreads();   // everyone done reading buffer (i&1)
        if (i + 2 < NST)
            issue_stage(i + 2);   // overwrites buffer (i&1) -- now safe
    }

    #pragma unroll
    for (int mt = 0; mt < 4; mt++) {
        int row = m0 + wm + mt * 16 + lq;
        #pragma unroll
        for (int nt = 0; nt < 4; nt++) {
            int col = n0 + wn + nt * 8 + lr * 2;
            *(float2*)(C + (size_t)row * N + col)       = make_float2(c[mt][nt][0], c[mt][nt][1]);
            *(float2*)(C + (size_t)(row + 8) * N + col) = make_float2(c[mt][nt][2], c[mt][nt][3]);
        }
    }
}

// Fused Q/K/V projection: blockIdx.z selects weight + destination.
__global__ __launch_bounds__(256, 2) void gemm_qkv(const float* __restrict__ x,
                                                   const float* __restrict__ wq,
                                                   const float* __restrict__ wk,
                                                   const float* __restrict__ wv)
{
    extern __shared__ float gsm[];
    const float* B = (blockIdx.z == 0) ? wq : (blockIdx.z == 1) ? wk : wv;
    float*       C = (blockIdx.z == 0) ? g_q : (blockIdx.z == 1) ? g_k : g_v;
    gemm_body(x, B, C, DIMN, DIMN, gsm);
}

// Generic single GEMM (output projection).
__global__ __launch_bounds__(256, 2) void gemm_tf32(const float* __restrict__ A,
                                                    const float* __restrict__ B,
                                                    float* __restrict__ C,
                                                    int M, int N, int K)
{
    extern __shared__ float gsm[];
    gemm_body(A, B, C, N, K, gsm);
}

// ---------------------------------------------------------------------------
// Tensor-core flash attention with FUSED RoPE on Q/K loads. (R8 version)
// ---------------------------------------------------------------------------
#define KSTR 132
#define VSTR 136
#define AT_SMEM ((2*128*128 + 64*KSTR + 64*VSTR) * 4)

__global__ __launch_bounds__(256, 1) void attn_tc(const float* __restrict__ fc,
                                                  const float* __restrict__ fs)
{
    extern __shared__ unsigned sm[];
    unsigned* Qhi = sm;
    unsigned* Qlo = sm + 128*128;
    unsigned* Ks  = sm + 2*128*128;
    unsigned* Vs  = Ks + 64*KSTR;

    const int tid  = threadIdx.x;
    const int wid  = tid >> 5;
    const int lane = tid & 31;
    const int lq   = lane >> 2;
    const int lr   = lane & 3;
    const int qt   = gridDim.x - 1 - blockIdx.x;
    const int h    = blockIdx.y;
    const int b    = blockIdx.z;
    const int q0   = qt * 128;
    const int R0   = wid * 16;

    const float* Qg = g_q + (size_t)(b*SEQ + q0) * DIMN + h * HD;
    const float* Kg = g_k + (size_t)(b*SEQ) * DIMN + h * HD;
    const float* Vg = g_v + (size_t)(b*SEQ) * DIMN + h * HD;

    const float qsc = 0.08838834764831845f;

    #pragma unroll
    for (int it = 0; it < 16; it++) {
        int i  = it * 256 + tid;
        int r  = i >> 5;
        int c4 = (i & 31) * 4;
        float4 v = *(const float4*)(Qg + (size_t)r * DIMN + c4);
        int s = q0 + r;
        int p = c4 >> 1;
        float c0 = fc[s*64 + p],     sn0 = fs[s*64 + p];
        float c1 = fc[s*64 + p + 1], sn1 = fs[s*64 + p + 1];
        float x0 = (v.x * c0 - v.y * sn0) * qsc;
        float y0 = (v.x * sn0 + v.y * c0) * qsc;
        float x1 = (v.z * c1 - v.w * sn1) * qsc;
        float y1 = (v.z * sn1 + v.w * c1) * qsc;
        unsigned h0 = f2tf32(x0), h1 = f2tf32(y0),
                 h2 = f2tf32(x1), h3 = f2tf32(y1);
        unsigned l0 = f2tf32(x0 - __uint_as_float(h0));
        unsigned l1 = f2tf32(y0 - __uint_as_float(h1));
        unsigned l2 = f2tf32(x1 - __uint_as_float(h2));
        unsigned l3 = f2tf32(y1 - __uint_as_float(h3));
        int blk = (c4 >> 2) ^ (r & 7);
        *(uint4*)&Qhi[r * 128 + blk * 4] = make_uint4(h0, h1, h2, h3);
        *(uint4*)&Qlo[r * 128 + blk * 4] = make_uint4(l0, l1, l2, l3);
    }

    float o[16][4];
    #pragma unroll
    for (int n = 0; n < 16; n++)
        #pragma unroll
        for (int r = 0; r < 4; r++) o[n][r] = 0.f;
    float m0r = -1e30f, m1r = -1e30f, l0r = 0.f, l1r = 0.f;

    const int nkt = 2 * qt + 2;
    for (int kt = 0; kt < nkt; kt++) {
        const int k0 = kt * 64;
        __syncthreads();

        #pragma unroll
        for (int it = 0; it < 8; it++) {
            int i  = it * 256 + tid;
            int r  = i >> 5;
            int c4 = (i & 31) * 4;
            float4 kv = *(const float4*)(Kg + (size_t)(k0 + r) * DIMN + c4);
            float4 vv = *(const float4*)(Vg + (size_t)(k0 + r) * DIMN + c4);
            int s = k0 + r;
            int p = c4 >> 1;
            float c0 = fc[s*64 + p],     sn0 = fs[s*64 + p];
            float c1 = fc[s*64 + p + 1], sn1 = fs[s*64 + p + 1];
            float x0 = kv.x * c0 - kv.y * sn0;
            float y0 = kv.x * sn0 + kv.y * c0;
            float x1 = kv.z * c1 - kv.w * sn1;
            float y1 = kv.z * sn1 + kv.w * c1;
            *(uint4*)&Ks[r * KSTR + c4] =
                make_uint4(f2tf32(x0), f2tf32(y0), f2tf32(x1), f2tf32(y1));
            *(uint4*)&Vs[r * VSTR + c4] =
                make_uint4(f2tf32(vv.x), f2tf32(vv.y), f2tf32(vv.z), f2tf32(vv.w));
        }
        __syncthreads();

        float s[8][4];
        #pragma unroll
        for (int j = 0; j < 8; j++)
            #pragma unroll
            for (int r = 0; r < 4; r++) s[j][r] = 0.f;

        #pragma unroll
        for (int ks = 0; ks < 16; ks++) {
            unsigned ah[4], al[4];
            int rA = (R0 + lq) * 128;
            int rB = (R0 + lq + 8) * 128;
            int blk0 = ((2*ks    ) ^ lq) * 4 + lr;
            int blk1 = ((2*ks + 1) ^ lq) * 4 + lr;
            ah[0] = Qhi[rA + blk0]; ah[1] = Qhi[rB + blk0];
            ah[2] = Qhi[rA + blk1]; ah[3] = Qhi[rB + blk1];
            al[0] = Qlo[rA + blk0]; al[1] = Qlo[rB + blk0];
            al[2] = Qlo[rA + blk1]; al[3] = Qlo[rB + blk1];
            #pragma unroll
            for (int j = 0; j < 8; j++) {
                unsigned bf[2];
                bf[0] = Ks[(8*j + lq) * KSTR + 8*ks + lr    ];
                bf[1] = Ks[(8*j + lq) * KSTR + 8*ks + lr + 4];
                mma_tf32(s[j], ah, bf);
                mma_tf32(s[j], al, bf);
            }
        }

        if (kt >= 2 * qt) {
            int grow0 = q0 + R0 + lq;
            int grow1 = grow0 + 8;
            #pragma unroll
            for (int j = 0; j < 8; j++) {
                int gc = k0 + 8*j + 2*lr;
                if (gc     > grow0) s[j][0] = -1e30f;
                if (gc + 1 > grow0) s[j][1] = -1e30f;
                if (gc     > grow1) s[j][2] = -1e30f;
                if (gc + 1 > grow1) s[j][3] = -1e30f;
            }
        }

        float mx0 = -1e30f, mx1 = -1e30f;
        #pragma unroll
        for (int j = 0; j < 8; j++) {
            mx0 = fmaxf(mx0, fmaxf(s[j][0], s[j][1]));
            mx1 = fmaxf(mx1, fmaxf(s[j][2], s[j][3]));
        }
        mx0 = fmaxf(mx0, __shfl_xor_sync(0xffffffffu, mx0, 1));
        mx0 = fmaxf(mx0, __shfl_xor_sync(0xffffffffu, mx0, 2));
        mx1 = fmaxf(mx1, __shfl_xor_sync(0xffffffffu, mx1, 1));
        mx1 = fmaxf(mx1, __shfl_xor_sync(0xffffffffu, mx1, 2));

        float mn0 = fmaxf(m0r, mx0), mn1 = fmaxf(m1r, mx1);
        float f0 = __expf(m0r - mn0), f1 = __expf(m1r - mn1);
        m0r = mn0; m1r = mn1;

        #pragma unroll
        for (int n = 0; n < 16; n++) {
            o[n][0] *= f0; o[n][1] *= f0;
            o[n][2] *= f1; o[n][3] *= f1;
        }

        float sum0 = 0.f, sum1 = 0.f;
        #pragma unroll
        for (int j = 0; j < 8; j++) {
            s[j][0] = __expf(s[j][0] - mn0);
            s[j][1] = __expf(s[j][1] - mn0);
            s[j][2] = __expf(s[j][2] - mn1);
            s[j][3] = __expf(s[j][3] - mn1);
            sum0 += s[j][0] + s[j][1];
            sum1 += s[j][2] + s[j][3];
        }
        sum0 += __shfl_xor_sync(0xffffffffu, sum0, 1);
        sum0 += __shfl_xor_sync(0xffffffffu, sum0, 2);
        sum1 += __shfl_xor_sync(0xffffffffu, sum1, 1);
        sum1 += __shfl_xor_sync(0xffffffffu, sum1, 2);
        l0r = l0r * f0 + sum0;
        l1r = l1r * f1 + sum1;

        const int srcA = lq * 4 + (lr >> 1);
        const int srcB = srcA + 2;
        const bool odd = (lr & 1);
        #pragma unroll
        for (int j = 0; j < 8; j++) {
            float t0 = __shfl_sync(0xffffffffu, s[j][0], srcA);
            float t1 = __shfl_sync(0xffffffffu, s[j][1], srcA);
            float t2 = __shfl_sync(0xffffffffu, s[j][2], srcA);
            float t3 = __shfl_sync(0xffffffffu, s[j][3], srcA);
            float u0 = __shfl_sync(0xffffffffu, s[j][0], srcB);
            float u1 = __shfl_sync(0xffffffffu, s[j][1], srcB);
            float u2 = __shfl_sync(0xffffffffu, s[j][2], srcB);
            float u3 = __shfl_sync(0xffffffffu, s[j][3], srcB);
            unsigned pa[4];
            pa[0] = f2tf32(odd ? t1 : t0);
            pa[1] = f2tf32(odd ? t3 : t2);
            pa[2] = f2tf32(odd ? u1 : u0);
            pa[3] = f2tf32(odd ? u3 : u2);
            #pragma unroll
            for (int n = 0; n < 16; n++) {
                unsigned bf[2];
                bf[0] = Vs[(8*j + lr    ) * VSTR + 8*n + lq];
                bf[1] = Vs[(8*j + lr + 4) * VSTR + 8*n + lq];
                mma_tf32(o[n], pa, bf);
            }
        }
    }

    float inv0 = 1.f / l0r, inv1 = 1.f / l1r;
    float* Og = g_att + (size_t)(b*SEQ + q0 + R0 + lq) * DIMN + h * HD;
    #pragma unroll
    for (int n = 0; n < 16; n++) {
        int col = 8*n + 2*lr;
        *(float2*)(Og + col) = make_float2(o[n][0]*inv0, o[n][1]*inv0);
        *(float2*)(Og + (size_t)8 * DIMN + col) = make_float2(o[n][2]*inv1, o[n][3]*inv1);
    }
}

// ---------------------------------------------------------------------------
// Launch
// ---------------------------------------------------------------------------
extern "C" void kernel_launch(void* const* d_in, const int* in_sizes, int n_in,
                              void* d_out, int out_size)
{
    const float* x  = (const float*)d_in[0];
    const float* fc = (const float*)d_in[2];
    const float* fs = (const float*)d_in[3];
    const float* wq = (const float*)d_in[5];
    const float* wk = (const float*)d_in[6];
    const float* wv = (const float*)d_in[7];
    const float* wo = (const float*)d_in[8];
    float* out = (float*)d_out;

    float* att;
    cudaGetSymbolAddress((void**)&att, g_att);

    cudaFuncSetAttribute(gemm_qkv,
                         cudaFuncAttributeMaxDynamicSharedMemorySize, GSMEM);
    cudaFuncSetAttribute(gemm_tf32,
                         cudaFuncAttributeMaxDynamicSharedMemorySize, GSMEM);
    cudaFuncSetAttribute(attn_tc,
                         cudaFuncAttributeMaxDynamicSharedMemorySize, AT_SMEM);

    dim3 gq(DIMN/128, ROWS/128, 3);    // (16, 32, 3)
    gemm_qkv<<<gq, 256, GSMEM>>>(x, wq, wk, wv);

    dim3 ga(SEQ/128, NH, BSZ);         // (16, 16, 2)
    attn_tc<<<ga, 256, AT_SMEM>>>(fc, fs);

    dim3 gg(DIMN/128, ROWS/128);       // (16, 32)
    gemm_tf32<<<gg, 256, GSMEM>>>(att, wo, out, ROWS, DIMN, DIMN);
}